// round 8
// baseline (speedup 1.0000x reference)
#include <cuda_runtime.h>
#include <cuda_bf16.h>
#include <math.h>

// ---------------- problem constants ----------------
#define BB 2
#define NN 2048
#define DD 128
#define HH 8
#define DH 16
#define LL 3
#define ROWS (BB*NN)        // 4096
#define SCALE 0.25f         // 1/sqrt(16)
#define LOG2E 1.4426950408889634f
#define NEGL  (-1.5e9f)     // masked logit, log2 domain
#define EPS   1e-5f
#define KS    8             // key-split chunks
#define CHUNK (NN/KS)       // 256 keys per chunk

// weight presplit offsets (uint elements)
#define OFF_IN   0
#define SZ_IN    (DD*DD)                    // 16384
#define OFF_QKV  (OFF_IN + SZ_IN)
#define SZ_QKV   (LL*3*DD*DD)               // 147456
#define OFF_OUT  (OFF_QKV + SZ_QKV)
#define SZ_OUT   (LL*DD*DD)                 // 49152
#define OFF_FF1  (OFF_OUT + SZ_OUT)
#define SZ_FF1   (LL*4*DD*DD)               // 196608
#define OFF_FF2  (OFF_FF1 + SZ_FF1)
#define SZ_FF2   (LL*DD*4*DD)               // 196608
#define W_TOTAL  (OFF_FF2 + SZ_FF2)         // 606208

typedef unsigned long long u64t;

__device__ __forceinline__ float ex2(float x) {
    float r; asm("ex2.approx.ftz.f32 %0,%1;" : "=f"(r) : "f"(x)); return r;
}
__device__ __forceinline__ unsigned tf32c(float x) {
    unsigned r; asm("cvt.rna.tf32.f32 %0,%1;" : "=r"(r) : "f"(x)); return r;
}
__device__ __forceinline__ void mma8(float c[4], unsigned a0, unsigned a1,
                                     unsigned a2, unsigned a3,
                                     unsigned b0, unsigned b1) {
    asm volatile(
        "mma.sync.aligned.m16n8k8.row.col.f32.tf32.tf32.f32 "
        "{%0,%1,%2,%3},{%4,%5,%6,%7},{%8,%9},{%0,%1,%2,%3};"
        : "+f"(c[0]), "+f"(c[1]), "+f"(c[2]), "+f"(c[3])
        : "r"(a0), "r"(a1), "r"(a2), "r"(a3), "r"(b0), "r"(b1));
}
__device__ __forceinline__ void tsplit(float x, unsigned& hi, unsigned& lo) {
    hi = tf32c(x);
    lo = tf32c(x - __uint_as_float(hi));
}
// f32x2 packed-math helpers (sm_100+)
__device__ __forceinline__ u64t f2pack(float x, float y) {
    u64t r; asm("mov.b64 %0,{%1,%2};" : "=l"(r) : "f"(x), "f"(y)); return r;
}
__device__ __forceinline__ float2 f2unpack(u64t v) {
    float2 r; asm("mov.b64 {%0,%1},%2;" : "=f"(r.x), "=f"(r.y) : "l"(v)); return r;
}
__device__ __forceinline__ u64t fma2(u64t a, u64t b, u64t c) {
    u64t d; asm("fma.rn.f32x2 %0,%1,%2,%3;" : "=l"(d) : "l"(a), "l"(b), "l"(c)); return d;
}
__device__ __forceinline__ u64t mul2(u64t a, u64t b) {
    u64t d; asm("mul.rn.f32x2 %0,%1,%2;" : "=l"(d) : "l"(a), "l"(b)); return d;
}
__device__ __forceinline__ u64t add2(u64t a, u64t b) {
    u64t d; asm("add.rn.f32x2 %0,%1,%2;" : "=l"(d) : "l"(a), "l"(b)); return d;
}

// ---------------- scratch (device globals; no allocation allowed) ----------
__device__ float g_h  [ROWS*DD];
__device__ float g_x  [ROWS*DD];
__device__ float g_qkv[ROWS*3*DD];
__device__ float g_o  [ROWS*DD];
__device__ float g_f  [ROWS*4*DD];
__device__ float g_pacc[ROWS*HH*KS*16];
__device__ float g_pml [ROWS*HH*KS*2];
__device__ float g_mean[ROWS];
__device__ float g_rstd[ROWS];
__device__ unsigned g_whi[W_TOTAL];
__device__ unsigned g_wlo[W_TOTAL];
__device__ int   g_isatom[ROWS];
__device__ int   g_mask  [ROWS];

// ---------------- merged weight presplit ----------------
// fp32 -> (hi,lo) tf32, k-interleaved. Since every region size/offset is a
// multiple of 8 and the interleave only permutes within 8-aligned groups,
// kin = gi & 7 globally.
__global__ void presplit_all_kernel(const float* __restrict__ w0, const float* __restrict__ w1,
                                    const float* __restrict__ w2, const float* __restrict__ w3,
                                    const float* __restrict__ w4,
                                    unsigned* __restrict__ hi, unsigned* __restrict__ lo) {
    int gi = blockIdx.x*blockDim.x + threadIdx.x;
    if (gi >= W_TOTAL) return;
    float v;
    if      (gi < OFF_QKV) v = w0[gi - OFF_IN];
    else if (gi < OFF_OUT) v = w1[gi - OFF_QKV];
    else if (gi < OFF_FF1) v = w2[gi - OFF_OUT];
    else if (gi < OFF_FF2) v = w3[gi - OFF_FF1];
    else                   v = w4[gi - OFF_FF2];
    int kin = gi & 7;
    int pos = (kin>>2) + 2*(kin&3);
    int dst = (gi - kin) + pos;
    unsigned h, l;
    tsplit(v, h, l);
    hi[dst] = h; lo[dst] = l;
}

// ---------------- bool normalization (format-agnostic) ----------------
__global__ void norm_bool_kernel(const unsigned char* __restrict__ raw, int count,
                                 int* __restrict__ out) {
    __shared__ int s_other;
    if (threadIdx.x == 0) s_other = 0;
    __syncthreads();
    const unsigned int* w = (const unsigned int*)raw;
    int nw = count / 4;
    int other = 0;
    for (int i = threadIdx.x; i < nw; i += blockDim.x) {
        unsigned int v = w[i];
        if (v != 0u && v != 1u && v != 0x3f800000u) other = 1;
    }
    if (other) atomicOr(&s_other, 1);
    __syncthreads();
    bool byteFmt = (s_other != 0);
    for (int i = threadIdx.x; i < count; i += blockDim.x) {
        out[i] = byteFmt ? (raw[i] != 0) : (w[i] != 0u);
    }
}

// ---------------- embedding gather ----------------
__global__ void embed_kernel(const float* __restrict__ atom_embed,
                             const float* __restrict__ cons_embed,
                             const int* __restrict__ atom_id,
                             const int* __restrict__ isatom,
                             float* __restrict__ e) {
    int row = blockIdx.x, t = threadIdx.x;
    int id = atom_id[row];
    id = id < 0 ? 0 : (id > 31 ? 31 : id);
    float v = isatom[row] ? atom_embed[id*DD + t] : cons_embed[t];
    e[row*DD + t] = v;
}

// ---------------- block reduction helper (128 threads) ----------------
__device__ __forceinline__ float blockReduceSum128(float v, float* sred) {
    #pragma unroll
    for (int o = 16; o; o >>= 1) v += __shfl_xor_sync(0xffffffffu, v, o);
    int wid = threadIdx.x >> 5;
    if ((threadIdx.x & 31) == 0) sred[wid] = v;
    __syncthreads();
    float r = sred[0] + sred[1] + sred[2] + sred[3];
    __syncthreads();
    return r;
}

// ---------------- LN stats: warp per row (shuffles only) ----------------
__global__ void stats_kernel(const float* __restrict__ in,
                             float* __restrict__ mean, float* __restrict__ rstd) {
    int gw = (blockIdx.x*blockDim.x + threadIdx.x) >> 5;
    int lane = threadIdx.x & 31;
    float4 v = *(const float4*)(in + (size_t)gw*DD + lane*4);
    float s  = v.x + v.y + v.z + v.w;
    float s2 = v.x*v.x + v.y*v.y + v.z*v.z + v.w*v.w;
    #pragma unroll
    for (int o = 16; o; o >>= 1) {
        s  += __shfl_xor_sync(0xffffffffu, s,  o);
        s2 += __shfl_xor_sync(0xffffffffu, s2, o);
    }
    if (lane == 0) {
        float mu = s * (1.0f/DD);
        mean[gw] = mu;
        rstd[gw] = rsqrtf(s2 * (1.0f/DD) - mu*mu + EPS);
    }
}

// ---------------- 3xTF32 tensor-core GEMM (pre-split W) ---------------------
template<int MODE, int TM, bool LNA>
__global__ __launch_bounds__(TM*4)
void gemm_tc(const float* __restrict__ A,
             const unsigned* __restrict__ Whi, const unsigned* __restrict__ Wlo,
             const float* __restrict__ bias, const float* __restrict__ res,
             float* __restrict__ C, int M, int Nc, int K,
             const float* __restrict__ meanp, const float* __restrict__ rstdp,
             const float* __restrict__ lng, const float* __restrict__ lnb) {
    constexpr int THREADS = TM*4;
    constexpr int AH = TM*32;          // uints per A half
    __shared__ unsigned As[2*TM*32];
    __shared__ unsigned Ws[2*64*32];
    const int t = threadIdx.x;
    const int w = t >> 5, lane = t & 31;
    const int g = lane >> 2, t4 = lane & 3;
    const int mw = (w >> 1) * 16, nw = (w & 1) * 32;
    const int m0 = blockIdx.y * TM, n0 = blockIdx.x * 64;

    float c[4][4];
    #pragma unroll
    for (int nt = 0; nt < 4; nt++)
        #pragma unroll
        for (int i = 0; i < 4; i++) c[nt][i] = 0.0f;

    for (int kb = 0; kb < K; kb += 32) {
        #pragma unroll
        for (int r = 0; r < (TM*8)/THREADS; r++) {
            int idx = t + r*THREADS;
            int row = idx >> 3, c4 = idx & 7;
            float4 va = *(const float4*)(A + (size_t)(m0+row)*K + kb + c4*4);
            if (LNA) {
                float mu = meanp[m0+row], rs = rstdp[m0+row];
                float4 g4 = *(const float4*)(lng + kb + c4*4);
                float4 b4 = *(const float4*)(lnb + kb + c4*4);
                va.x = (va.x - mu)*rs*g4.x + b4.x;
                va.y = (va.y - mu)*rs*g4.y + b4.y;
                va.z = (va.z - mu)*rs*g4.z + b4.z;
                va.w = (va.w - mu)*rs*g4.w + b4.w;
            }
            unsigned* dh = As + (c4>>1)*(TM*8) + row*8 + (c4&1);
            unsigned h0,l0,h1,l1,h2,l2,h3,l3;
            tsplit(va.x,h0,l0); tsplit(va.y,h1,l1);
            tsplit(va.z,h2,l2); tsplit(va.w,h3,l3);
            dh[0]=h0; dh[2]=h1; dh[4]=h2; dh[6]=h3;
            dh[AH+0]=l0; dh[AH+2]=l1; dh[AH+4]=l2; dh[AH+6]=l3;
        }
        #pragma unroll
        for (int r = 0; r < 512/THREADS; r++) {
            int idx = t + r*THREADS;
            int row = idx >> 3, c4 = idx & 7;
            size_t src = (size_t)(n0+row)*K + kb + c4*4;
            int dst = (c4>>1)*512 + row*8 + (c4&1)*4;
            *(uint4*)(Ws + dst)        = *(const uint4*)(Whi + src);
            *(uint4*)(Ws + 2048 + dst) = *(const uint4*)(Wlo + src);
        }
        __syncthreads();
        #pragma unroll
        for (int kc = 0; kc < 4; kc++) {
            const uint2* A2h = (const uint2*)(As + kc*(TM*8));
            const uint2* A2l = (const uint2*)(As + AH + kc*(TM*8));
            const uint2* W2h = (const uint2*)(Ws + kc*512);
            const uint2* W2l = (const uint2*)(Ws + 2048 + kc*512);
            uint2 aHlo, aHhi, aLlo, aLhi, bH[4], bL[4];
            {
                int r0 = (mw + g)*4 + t4;
                int r8 = (mw + 8 + g)*4 + t4;
                aHlo = A2h[r0]; aHhi = A2h[r8];
                aLlo = A2l[r0]; aLhi = A2l[r8];
            }
            #pragma unroll
            for (int nt = 0; nt < 4; nt++) {
                int rb = (nw + nt*8 + g)*4 + t4;
                bH[nt] = W2h[rb]; bL[nt] = W2l[rb];
            }
            #pragma unroll
            for (int nt = 0; nt < 4; nt++) {
                mma8(c[nt], aHlo.x, aHhi.x, aHlo.y, aHhi.y, bH[nt].x, bH[nt].y);
                mma8(c[nt], aLlo.x, aLhi.x, aLlo.y, aLhi.y, bH[nt].x, bH[nt].y);
                mma8(c[nt], aHlo.x, aHhi.x, aHlo.y, aHhi.y, bL[nt].x, bL[nt].y);
            }
        }
        __syncthreads();
    }
    #pragma unroll
    for (int nt = 0; nt < 4; nt++) {
        int col = n0 + nw + nt*8 + t4*2;
        float2 b2 = *(const float2*)(bias + col);
        #pragma unroll
        for (int half = 0; half < 2; half++) {
            int row = m0 + mw + g + half*8;
            float vx = c[nt][half*2]   + b2.x;
            float vy = c[nt][half*2+1] + b2.y;
            size_t off = (size_t)row*Nc + col;
            if (MODE == 1) {
                float2 rv = *(const float2*)(res + off);
                vx += rv.x; vy += rv.y;
            }
            if (MODE == 2) {
                vx = 0.5f*vx*(1.0f + erff(vx*0.70710678118654752f));
                vy = 0.5f*vy*(1.0f + erff(vy*0.70710678118654752f));
            }
            *(float2*)(C + off) = make_float2(vx, vy);
        }
    }
}

// ---------------- split-K flash attention (partials, f32x2, 2-key pairs) ---
// Grid: (N/64, KS*B), 512 threads. Thread (h=tid>>6, qi=tid&63) owns one
// (head, query-row). NOTE: no min-blocks launch_bounds clause — a register
// cap here causes catastrophic spills (R3 lesson).
__global__ __launch_bounds__(512)
void attn_part_kernel(const float* __restrict__ qkv, const float* __restrict__ adj,
                      const int* __restrict__ mask, const float* __restrict__ sbp,
                      float* __restrict__ pacc, float* __restrict__ pml) {
    extern __shared__ float sm[];
    float* sK    = sm;                    // 64*128
    float* sV    = sK + 64*128;           // 64*128
    float* sBias = sV + 64*128;           // 64*65  (kj-major, padded)

    const int b = blockIdx.y >> 3, ck = blockIdx.y & 7;
    const int n0 = blockIdx.x * 64;
    const int tid = threadIdx.x;
    const int qi = tid & 63, hh = tid >> 6;
    const float sbl = (*sbp) * LOG2E;
    const float SC2 = SCALE * LOG2E;

    const int qrow = b*NN + n0 + qi;
    u64t q2[8];
    {
        const ulonglong2* qp = (const ulonglong2*)(qkv + (size_t)qrow*384 + hh*DH);
        #pragma unroll
        for (int i = 0; i < 4; i++) { ulonglong2 v = qp[i]; q2[2*i] = v.x; q2[2*i+1] = v.y; }
    }

    float m = -INFINITY, l = 0.0f;
    u64t acc2[8];
    #pragma unroll
    for (int d = 0; d < 8; d++) acc2[d] = 0ull;

    const float* adjb = adj + (size_t)b*NN*NN;
    const int* maskb = mask + b*NN;

    for (int k0 = ck*CHUNK; k0 < (ck+1)*CHUNK; k0 += 64) {
        #pragma unroll
        for (int r = 0; r < 4; r++) {
            int idx = tid + r*512;
            int row = idx >> 5, c4 = idx & 31;
            const float* base = qkv + (size_t)(b*NN + k0 + row)*384;
            *(float4*)(sK + row*128 + c4*4) = *(const float4*)(base + 128 + c4*4);
            *(float4*)(sV + row*128 + c4*4) = *(const float4*)(base + 256 + c4*4);
        }
        #pragma unroll
        for (int r = 0; r < 8; r++) {
            int idx = tid + r*512;
            int q2i = idx >> 6, kj = idx & 63;
            int mq = maskb[n0 + q2i], mk2 = maskb[k0 + kj];
            bool ok = (mq && mk2) || (!mq && (n0 + q2i == k0 + kj));
            float v = sbl * adjb[(size_t)(n0 + q2i)*NN + k0 + kj];
            sBias[kj*65 + q2i] = ok ? v : v + NEGL;
        }
        __syncthreads();

        for (int kj = 0; kj < 64; kj += 2) {
            const ulonglong2* kp0 = (const ulonglong2*)(sK + kj*128 + hh*DH);
            const ulonglong2* kp1 = (const ulonglong2*)(sK + (kj+1)*128 + hh*DH);
            u64t s0a = 0ull, s0b = 0ull, s1a = 0ull, s1b = 0ull;
            #pragma unroll
            for (int i = 0; i < 4; i++) {
                ulonglong2 k0v = kp0[i], k1v = kp1[i];
                s0a = fma2(q2[2*i],   k0v.x, s0a);
                s0b = fma2(q2[2*i+1], k0v.y, s0b);
                s1a = fma2(q2[2*i],   k1v.x, s1a);
                s1b = fma2(q2[2*i+1], k1v.y, s1b);
            }
            float2 u0 = f2unpack(add2(s0a, s0b));
            float2 u1 = f2unpack(add2(s1a, s1b));
            float s0 = fmaf(u0.x + u0.y, SC2, sBias[kj*65 + qi]);
            float s1 = fmaf(u1.x + u1.y, SC2, sBias[(kj+1)*65 + qi]);

            float mn = fmaxf(m, fmaxf(s0, s1));
            if (mn > m) {
                float corr = ex2(m - mn);
                l *= corr;
                u64t c2 = f2pack(corr, corr);
                #pragma unroll
                for (int d = 0; d < 8; d++) acc2[d] = mul2(acc2[d], c2);
                m = mn;
            }
            float p0 = ex2(s0 - m);
            float p1 = ex2(s1 - m);
            l += p0 + p1;
            u64t p02 = f2pack(p0, p0), p12 = f2pack(p1, p1);
            const ulonglong2* vp0 = (const ulonglong2*)(sV + kj*128 + hh*DH);
            const ulonglong2* vp1 = (const ulonglong2*)(sV + (kj+1)*128 + hh*DH);
            #pragma unroll
            for (int i = 0; i < 4; i++) {
                ulonglong2 v0 = vp0[i], v1 = vp1[i];
                acc2[2*i]   = fma2(p02, v0.x, acc2[2*i]);
                acc2[2*i+1] = fma2(p02, v0.y, acc2[2*i+1]);
                acc2[2*i]   = fma2(p12, v1.x, acc2[2*i]);
                acc2[2*i+1] = fma2(p12, v1.y, acc2[2*i+1]);
            }
        }
        __syncthreads();
    }
    size_t p = ((size_t)qrow*HH + hh)*KS + ck;
    pml[p*2]   = m;
    pml[p*2+1] = l;
    #pragma unroll
    for (int d = 0; d < 8; d++) {
        float2 v = f2unpack(acc2[d]);
        pacc[p*16 + 2*d]   = v.x;
        pacc[p*16 + 2*d+1] = v.y;
    }
}

// ---------------- split-K reduce (base-2 weights) ----------------
__global__ void attn_reduce_kernel(const float* __restrict__ pacc,
                                   const float* __restrict__ pml,
                                   float* __restrict__ o) {
    int t = blockIdx.x * blockDim.x + threadIdx.x;     // 0..ROWS*HH-1
    if (t >= ROWS*HH) return;
    size_t base = (size_t)t * KS;
    float mv[KS], lv[KS];
    float M = -INFINITY;
    #pragma unroll
    for (int c = 0; c < KS; c++) {
        mv[c] = pml[(base+c)*2];
        lv[c] = pml[(base+c)*2+1];
        M = fmaxf(M, mv[c]);
    }
    float w[KS]; float L = 0.0f;
    #pragma unroll
    for (int c = 0; c < KS; c++) { w[c] = ex2(mv[c] - M); L += w[c]*lv[c]; }
    float inv = 1.0f / L;
    int qrow = t >> 3, hh = t & 7;
    float* op = o + (size_t)qrow*DD + hh*DH;
    #pragma unroll
    for (int d = 0; d < 16; d++) {
        float s = 0.0f;
        #pragma unroll
        for (int c = 0; c < KS; c++) s += w[c] * pacc[(base+c)*16 + d];
        op[d] = s * inv;
    }
}

// ---------------- head: gather root, LN, dot ----------------
__global__ void head_kernel(const float* __restrict__ h, const float* __restrict__ g,
                            const float* __restrict__ bb, const float* __restrict__ w,
                            const float* __restrict__ hb, const int* __restrict__ root,
                            float* __restrict__ out) {
    __shared__ float sred[4];
    int t = threadIdx.x;
    for (int b = 0; b < BB; b++) {
        int row = root[b];
        float v = h[((size_t)b*NN + row)*DD + t];
        float mean = blockReduceSum128(v, sred) * (1.0f/DD);
        float d = v - mean;
        float var = blockReduceSum128(d*d, sred) * (1.0f/DD);
        float p = d * rsqrtf(var + EPS) * g[t] + bb[t];
        float s = blockReduceSum128(p * w[t], sred);
        if (t == 0) out[b] = s + hb[0];
    }
}

// ---------------- launch ----------------
extern "C" void kernel_launch(void* const* d_in, const int* in_sizes, int n_in,
                              void* d_out, int out_size) {
    const float* atom_embed = (const float*)d_in[0];
    const float* cons_embed = (const float*)d_in[1];
    const float* in_w   = (const float*)d_in[2];
    const float* in_b   = (const float*)d_in[3];
    const float* qkv_w  = (const float*)d_in[4];
    const float* qkv_b  = (const float*)d_in[5];
    const float* out_w  = (const float*)d_in[6];
    const float* out_b  = (const float*)d_in[7];
    const float* ln1_g  = (const float*)d_in[8];
    const float* ln1_b  = (const float*)d_in[9];
    const float* ln2_g  = (const float*)d_in[10];
    const float* ln2_b  = (const float*)d_in[11];
    const float* ff1_w  = (const float*)d_in[12];
    const float* ff1_b  = (const float*)d_in[13];
    const float* ff2_w  = (const float*)d_in[14];
    const float* ff2_b  = (const float*)d_in[15];
    const float* struct_bias = (const float*)d_in[16];
    const float* head_ln_g = (const float*)d_in[17];
    const float* head_ln_b = (const float*)d_in[18];
    const float* head_w = (const float*)d_in[19];
    const float* head_b = (const float*)d_in[20];
    const float* adjacency = (const float*)d_in[21];
    const unsigned char* is_atom_raw = (const unsigned char*)d_in[22];
    const int* atom_id  = (const int*)d_in[23];
    const unsigned char* mask_raw = (const unsigned char*)d_in[24];
    const int* root_idx = (const int*)d_in[25];
    float* outp = (float*)d_out;

    float *h, *x, *qkv, *o, *f, *pacc, *pml, *mean, *rstd;
    unsigned *whi, *wlo;
    int *im, *mk;
    cudaGetSymbolAddress((void**)&h,  g_h);
    cudaGetSymbolAddress((void**)&x,  g_x);
    cudaGetSymbolAddress((void**)&qkv, g_qkv);
    cudaGetSymbolAddress((void**)&o,  g_o);
    cudaGetSymbolAddress((void**)&f,  g_f);
    cudaGetSymbolAddress((void**)&pacc, g_pacc);
    cudaGetSymbolAddress((void**)&pml,  g_pml);
    cudaGetSymbolAddress((void**)&mean, g_mean);
    cudaGetSymbolAddress((void**)&rstd, g_rstd);
    cudaGetSymbolAddress((void**)&whi, g_whi);
    cudaGetSymbolAddress((void**)&wlo, g_wlo);
    cudaGetSymbolAddress((void**)&im, g_isatom);
    cudaGetSymbolAddress((void**)&mk, g_mask);

    const int ATTN_SMEM = (64*128*2 + 64*65)*4;
    cudaFuncSetAttribute(attn_part_kernel, cudaFuncAttributeMaxDynamicSharedMemorySize, ATTN_SMEM);

    presplit_all_kernel<<<(W_TOTAL+255)/256, 256>>>(in_w, qkv_w, out_w, ff1_w, ff2_w, whi, wlo);

    norm_bool_kernel<<<1, 256>>>(is_atom_raw, ROWS, im);
    norm_bool_kernel<<<1, 256>>>(mask_raw,    ROWS, mk);
    embed_kernel<<<ROWS, 128>>>(atom_embed, cons_embed, atom_id, im, x);

    gemm_tc<0,32,false><<<dim3(2,128), 128>>>(x, whi+OFF_IN, wlo+OFF_IN, in_b, nullptr, h,
                                              ROWS, DD, DD, nullptr, nullptr, nullptr, nullptr);

    for (int l = 0; l < LL; l++) {
        stats_kernel<<<ROWS/8, 256>>>(h, mean, rstd);
        gemm_tc<0,64,true><<<dim3(6,64), 256>>>(h, whi+OFF_QKV + l*3*DD*DD, wlo+OFF_QKV + l*3*DD*DD,
                                                qkv_b + l*3*DD, nullptr, qkv,
                                                ROWS, 3*DD, DD,
                                                mean, rstd, ln1_g + l*DD, ln1_b + l*DD);
        attn_part_kernel<<<dim3(NN/64, KS*BB), 512, ATTN_SMEM>>>(qkv, adjacency, mk,
                                                                 struct_bias + l, pacc, pml);
        attn_reduce_kernel<<<ROWS*HH/256, 256>>>(pacc, pml, o);
        gemm_tc<1,32,false><<<dim3(2,128), 128>>>(o, whi+OFF_OUT + l*DD*DD, wlo+OFF_OUT + l*DD*DD,
                                                  out_b + l*DD, h, h,
                                                  ROWS, DD, DD, nullptr, nullptr, nullptr, nullptr);
        stats_kernel<<<ROWS/8, 256>>>(h, mean, rstd);
        gemm_tc<2,64,true><<<dim3(8,64), 256>>>(h, whi+OFF_FF1 + l*4*DD*DD, wlo+OFF_FF1 + l*4*DD*DD,
                                                ff1_b + l*4*DD, nullptr, f,
                                                ROWS, 4*DD, DD,
                                                mean, rstd, ln2_g + l*DD, ln2_b + l*DD);
        gemm_tc<1,32,false><<<dim3(2,128), 128>>>(f, whi+OFF_FF2 + l*DD*4*DD, wlo+OFF_FF2 + l*DD*4*DD,
                                                  ff2_b + l*DD, h, h,
                                                  ROWS, DD, 4*DD, nullptr, nullptr, nullptr, nullptr);
    }

    head_kernel<<<1, 128>>>(h, head_ln_g, head_ln_b, head_w, head_b, root_idx, outp);
}

// round 9
// speedup vs baseline: 1.2378x; 1.2378x over previous
#include <cuda_runtime.h>
#include <cuda_bf16.h>
#include <math.h>

// ---------------- problem constants ----------------
#define BB 2
#define NN 2048
#define DD 128
#define HH 8
#define DH 16
#define LL 3
#define ROWS (BB*NN)        // 4096
#define SCALE 0.25f         // 1/sqrt(16)
#define LOG2E 1.4426950408889634f
#define NEGL  (-1.5e9f)     // masked logit, log2 domain
#define EPS   1e-5f
#define KS    8             // key-split chunks
#define CHUNK (NN/KS)       // 256 keys per chunk

__device__ __forceinline__ float ex2(float x) {
    float r; asm("ex2.approx.ftz.f32 %0,%1;" : "=f"(r) : "f"(x)); return r;
}
__device__ __forceinline__ unsigned tf32c(float x) {
    unsigned r; asm("cvt.rna.tf32.f32 %0,%1;" : "=r"(r) : "f"(x)); return r;
}
__device__ __forceinline__ void mma8(float c[4], unsigned a0, unsigned a1,
                                     unsigned a2, unsigned a3,
                                     unsigned b0, unsigned b1) {
    asm volatile(
        "mma.sync.aligned.m16n8k8.row.col.f32.tf32.tf32.f32 "
        "{%0,%1,%2,%3},{%4,%5,%6,%7},{%8,%9},{%0,%1,%2,%3};"
        : "+f"(c[0]), "+f"(c[1]), "+f"(c[2]), "+f"(c[3])
        : "r"(a0), "r"(a1), "r"(a2), "r"(a3), "r"(b0), "r"(b1));
}
__device__ __forceinline__ void tsplit(float x, unsigned& hi, unsigned& lo) {
    hi = tf32c(x);
    lo = tf32c(x - __uint_as_float(hi));
}

// ---------------- scratch (device globals; no allocation allowed) ----------
__device__ float g_h  [ROWS*DD];
__device__ float g_x  [ROWS*DD];
__device__ float g_qkv[ROWS*3*DD];
__device__ float g_o  [ROWS*DD];
__device__ float g_f  [ROWS*4*DD];
__device__ float g_pacc[ROWS*HH*KS*16];
__device__ float g_pml [ROWS*HH*KS*2];
__device__ float g_mean[ROWS];
__device__ float g_rstd[ROWS];
__device__ int   g_isatom[ROWS];
__device__ int   g_mask  [ROWS];

// ---------------- bool normalization (format-agnostic) ----------------
__global__ void norm_bool_kernel(const unsigned char* __restrict__ raw, int count,
                                 int* __restrict__ out) {
    __shared__ int s_other;
    if (threadIdx.x == 0) s_other = 0;
    __syncthreads();
    const unsigned int* w = (const unsigned int*)raw;
    int nw = count / 4;
    int other = 0;
    for (int i = threadIdx.x; i < nw; i += blockDim.x) {
        unsigned int v = w[i];
        if (v != 0u && v != 1u && v != 0x3f800000u) other = 1;
    }
    if (other) atomicOr(&s_other, 1);
    __syncthreads();
    bool byteFmt = (s_other != 0);
    for (int i = threadIdx.x; i < count; i += blockDim.x) {
        out[i] = byteFmt ? (raw[i] != 0) : (w[i] != 0u);
    }
}

// ---------------- embedding gather ----------------
__global__ void embed_kernel(const float* __restrict__ atom_embed,
                             const float* __restrict__ cons_embed,
                             const int* __restrict__ atom_id,
                             const int* __restrict__ isatom,
                             float* __restrict__ e) {
    int row = blockIdx.x, t = threadIdx.x;
    int id = atom_id[row];
    id = id < 0 ? 0 : (id > 31 ? 31 : id);
    float v = isatom[row] ? atom_embed[id*DD + t] : cons_embed[t];
    e[row*DD + t] = v;
}

// ---------------- block reduction helper (128 threads) ----------------
__device__ __forceinline__ float blockReduceSum128(float v, float* sred) {
    #pragma unroll
    for (int o = 16; o; o >>= 1) v += __shfl_xor_sync(0xffffffffu, v, o);
    int wid = threadIdx.x >> 5;
    if ((threadIdx.x & 31) == 0) sred[wid] = v;
    __syncthreads();
    float r = sred[0] + sred[1] + sred[2] + sred[3];
    __syncthreads();
    return r;
}

// ---------------- LN stats: warp per row (shuffles only) ----------------
__global__ void stats_kernel(const float* __restrict__ in,
                             float* __restrict__ mean, float* __restrict__ rstd) {
    int gw = (blockIdx.x*blockDim.x + threadIdx.x) >> 5;
    int lane = threadIdx.x & 31;
    float4 v = *(const float4*)(in + (size_t)gw*DD + lane*4);
    float s  = v.x + v.y + v.z + v.w;
    float s2 = v.x*v.x + v.y*v.y + v.z*v.z + v.w*v.w;
    #pragma unroll
    for (int o = 16; o; o >>= 1) {
        s  += __shfl_xor_sync(0xffffffffu, s,  o);
        s2 += __shfl_xor_sync(0xffffffffu, s2, o);
    }
    if (lane == 0) {
        float mu = s * (1.0f/DD);
        mean[gw] = mu;
        rstd[gw] = rsqrtf(s2 * (1.0f/DD) - mu*mu + EPS);
    }
}

// ---------------- SIMT GEMM (R4 lineage — proven fastest config) -----------
// C[M,Nc] = A'[M,K] @ W[Nc,K]^T + bias (+epilogue); A' = optional LayerNorm.
// MODE 0: +bias | MODE 1: +bias +res (res may alias C) | MODE 2: +bias, GELU
template<int MODE, int TM, bool LNA>
__global__ __launch_bounds__(256)
void gemm_kernel(const float* __restrict__ A, const float* __restrict__ W,
                 const float* __restrict__ bias, const float* __restrict__ res,
                 float* __restrict__ C, int M, int Nc, int K,
                 const float* __restrict__ meanp, const float* __restrict__ rstdp,
                 const float* __restrict__ lng, const float* __restrict__ lnb) {
    __shared__ float As[TM*33];
    __shared__ float Ws[64*33];
    const int t = threadIdx.x;
    const int tx = t & 15, ty = t >> 4;
    const int m0 = blockIdx.y * TM, n0 = blockIdx.x * 64;
    constexpr int RM = TM / 16;
    float acc[RM][4] = {};

    for (int k0 = 0; k0 < K; k0 += 32) {
        #pragma unroll
        for (int r = 0; r < TM/32; r++) {
            int idx = t + r*256;
            int row = idx >> 3, c4 = idx & 7;
            float4 va = *(const float4*)(A + (size_t)(m0+row)*K + k0 + c4*4);
            if (LNA) {
                float mu = meanp[m0+row], rs = rstdp[m0+row];
                float4 g4 = *(const float4*)(lng + k0 + c4*4);
                float4 b4 = *(const float4*)(lnb + k0 + c4*4);
                va.x = (va.x - mu)*rs*g4.x + b4.x;
                va.y = (va.y - mu)*rs*g4.y + b4.y;
                va.z = (va.z - mu)*rs*g4.z + b4.z;
                va.w = (va.w - mu)*rs*g4.w + b4.w;
            }
            float* da = As + row*33 + c4*4;
            da[0]=va.x; da[1]=va.y; da[2]=va.z; da[3]=va.w;
        }
        #pragma unroll
        for (int r = 0; r < 2; r++) {
            int idx = t + r*256;
            int row = idx >> 3, c4 = idx & 7;
            float4 vb = *(const float4*)(W + (size_t)(n0+row)*K + k0 + c4*4);
            float* db = Ws + row*33 + c4*4;
            db[0]=vb.x; db[1]=vb.y; db[2]=vb.z; db[3]=vb.w;
        }
        __syncthreads();
        #pragma unroll
        for (int kk = 0; kk < 32; kk++) {
            float a[RM], w[4];
            #pragma unroll
            for (int i = 0; i < RM; i++) a[i] = As[(ty*RM+i)*33 + kk];
            #pragma unroll
            for (int j = 0; j < 4; j++) w[j] = Ws[(tx*4+j)*33 + kk];
            #pragma unroll
            for (int i = 0; i < RM; i++)
                #pragma unroll
                for (int j = 0; j < 4; j++)
                    acc[i][j] += a[i] * w[j];
        }
        __syncthreads();
    }
    #pragma unroll
    for (int i = 0; i < RM; i++) {
        int r = m0 + ty*RM + i;
        #pragma unroll
        for (int j = 0; j < 4; j++) {
            int c = n0 + tx*4 + j;
            float v = acc[i][j] + bias[c];
            if (MODE == 1) v += res[(size_t)r*Nc + c];
            if (MODE == 2) v = 0.5f * v * (1.0f + erff(v * 0.70710678118654752f));
            C[(size_t)r*Nc + c] = v;
        }
    }
}

// ---------------- hybrid attention: MMA scores + scalar softmax/PV ---------
// Grid (N/64, KS*B), 512 threads (16 warps).
// Per 32-key tile: warp w = (head w>>1, q-half w&1) computes S[32q,32k] for
// its head via 3xTF32 m16n8k8 (fp32-grade), folds SCALE/adj/mask into S in
// smem. Then thread (hh=tid>>6, qi=tid&63) runs R4's scalar online softmax
// + PV reading s from smem.
__global__ __launch_bounds__(512)
void attn_part_kernel(const float* __restrict__ qkv, const float* __restrict__ adj,
                      const int* __restrict__ mask, const float* __restrict__ sbp,
                      float* __restrict__ pacc, float* __restrict__ pml) {
    extern __shared__ float sm[];
    float* sK  = sm;              // 32 x pitch132
    float* sV  = sm + 4224;       // 32 x pitch132
    float* sS  = sm + 8448;       // 8 heads x 64q x pitch33
    int*  sMq  = (int*)(sm + 25344);  // 64
    int*  sMk  = (int*)(sm + 25408);  // 32

    const int b = blockIdx.y >> 3, ck = blockIdx.y & 7;
    const int n0 = blockIdx.x * 64;
    const int tid = threadIdx.x;
    const int w = tid >> 5, lane = tid & 31;
    const int g = lane >> 2, t4 = lane & 3;
    const int hh_m = w >> 1, mhalf = w & 1;     // MMA identity
    const int qi = tid & 63, hh = tid >> 6;     // scalar identity
    const float sbl = (*sbp) * LOG2E;
    const float SC2 = SCALE * LOG2E;

    const float* adjb = adj + (size_t)b*NN*NN;
    const int* maskb = mask + b*NN;

    // q-row masks (once per block)
    if (tid < 64) sMq[tid] = maskb[n0 + tid];

    // hoisted Q A-fragments (hi/lo), rows = mhalf*32 + mt*16 + {g, g+8}
    unsigned aqh[2][2][4], aql[2][2][4];
    #pragma unroll
    for (int mt = 0; mt < 2; mt++)
        #pragma unroll
        for (int ks = 0; ks < 2; ks++) {
            const float* base0 = qkv + (size_t)(b*NN + n0 + mhalf*32 + mt*16 + g)*384 + hh_m*DH + ks*8;
            const float* base8 = base0 + 8*384;
            tsplit(base0[t4],   aqh[mt][ks][0], aql[mt][ks][0]);
            tsplit(base8[t4],   aqh[mt][ks][1], aql[mt][ks][1]);
            tsplit(base0[t4+4], aqh[mt][ks][2], aql[mt][ks][2]);
            tsplit(base8[t4+4], aqh[mt][ks][3], aql[mt][ks][3]);
        }

    float m = -INFINITY, l = 0.0f;
    float acc[16];
    #pragma unroll
    for (int d = 0; d < 16; d++) acc[d] = 0.0f;

    for (int k0 = ck*CHUNK; k0 < (ck+1)*CHUNK; k0 += 32) {
        // ---- stage K/V tile (32 rows x 128, pitch 132) ----
        #pragma unroll
        for (int r = 0; r < 2; r++) {
            int idx = tid + r*512;           // 1024 float4 slots
            int row = idx >> 5, c4 = idx & 31;
            const float* base = qkv + (size_t)(b*NN + k0 + row)*384;
            *(float4*)(sK + row*132 + c4*4) = *(const float4*)(base + 128 + c4*4);
            *(float4*)(sV + row*132 + c4*4) = *(const float4*)(base + 256 + c4*4);
        }
        if (tid < 32) sMk[tid] = maskb[k0 + tid];
        __syncthreads();

        // ---- MMA phase: S[32q, 32k] per warp ----
        {
            float c[2][4][4];
            #pragma unroll
            for (int mt = 0; mt < 2; mt++)
                #pragma unroll
                for (int nt = 0; nt < 4; nt++)
                    #pragma unroll
                    for (int i = 0; i < 4; i++) c[mt][nt][i] = 0.0f;

            #pragma unroll
            for (int ks = 0; ks < 2; ks++)
                #pragma unroll
                for (int nt = 0; nt < 4; nt++) {
                    const float* kb = sK + (nt*8 + g)*132 + hh_m*DH + ks*8;
                    unsigned bh0, bl0, bh1, bl1;
                    tsplit(kb[t4],   bh0, bl0);
                    tsplit(kb[t4+4], bh1, bl1);
                    #pragma unroll
                    for (int mt = 0; mt < 2; mt++) {
                        mma8(c[mt][nt], aqh[mt][ks][0], aqh[mt][ks][1], aqh[mt][ks][2], aqh[mt][ks][3], bh0, bh1);
                        mma8(c[mt][nt], aql[mt][ks][0], aql[mt][ks][1], aql[mt][ks][2], aql[mt][ks][3], bh0, bh1);
                        mma8(c[mt][nt], aqh[mt][ks][0], aqh[mt][ks][1], aqh[mt][ks][2], aqh[mt][ks][3], bl0, bl1);
                    }
                }

            // epilogue: S = c*SC2 + sbl*adj + mask  -> sS[hh][q][k]
            #pragma unroll
            for (int mt = 0; mt < 2; mt++)
                #pragma unroll
                for (int nt = 0; nt < 4; nt++)
                    #pragma unroll
                    for (int half = 0; half < 2; half++) {
                        int qloc = mhalf*32 + mt*16 + g + half*8;
                        int kk = nt*8 + t4*2;
                        int gq = n0 + qloc, gk = k0 + kk;
                        float2 a2 = *(const float2*)(adjb + (size_t)gq*NN + gk);
                        int mq = sMq[qloc];
                        bool ok0 = (mq && sMk[kk])   || (!mq && gq == gk);
                        bool ok1 = (mq && sMk[kk+1]) || (!mq && gq == gk+1);
                        float v0 = fmaf(c[mt][nt][half*2],   SC2, sbl*a2.x) + (ok0 ? 0.0f : NEGL);
                        float v1 = fmaf(c[mt][nt][half*2+1], SC2, sbl*a2.y) + (ok1 ? 0.0f : NEGL);
                        float* dst = sS + hh_m*2112 + qloc*33 + kk;
                        dst[0] = v0; dst[1] = v1;
                    }
        }
        __syncthreads();

        // ---- scalar phase: online softmax + PV (reads sS, sV) ----
        const float* srow = sS + hh*2112 + qi*33;
        for (int kj = 0; kj < 32; kj += 2) {
            float s0 = srow[kj];
            float s1 = srow[kj+1];
            float mn = fmaxf(m, fmaxf(s0, s1));
            if (mn > m) {
                float corr = ex2(m - mn);
                l *= corr;
                #pragma unroll
                for (int d = 0; d < 16; d++) acc[d] *= corr;
                m = mn;
            }
            float p0 = ex2(s0 - m);
            float p1 = ex2(s1 - m);
            l += p0 + p1;
            const float4* vp0 = (const float4*)(sV + kj*132 + hh*DH);
            const float4* vp1 = (const float4*)(sV + (kj+1)*132 + hh*DH);
            #pragma unroll
            for (int i = 0; i < 4; i++) {
                float4 v0 = vp0[i], v1 = vp1[i];
                acc[i*4+0] += p0*v0.x + p1*v1.x;
                acc[i*4+1] += p0*v0.y + p1*v1.y;
                acc[i*4+2] += p0*v0.z + p1*v1.z;
                acc[i*4+3] += p0*v0.w + p1*v1.w;
            }
        }
        __syncthreads();
    }
    const int qrow = b*NN + n0 + qi;
    size_t p = ((size_t)qrow*HH + hh)*KS + ck;
    pml[p*2]   = m;
    pml[p*2+1] = l;
    #pragma unroll
    for (int d = 0; d < 16; d++) pacc[p*16 + d] = acc[d];
}

// ---------------- split-K reduce (base-2 weights) ----------------
__global__ void attn_reduce_kernel(const float* __restrict__ pacc,
                                   const float* __restrict__ pml,
                                   float* __restrict__ o) {
    int t = blockIdx.x * blockDim.x + threadIdx.x;     // 0..ROWS*HH-1
    if (t >= ROWS*HH) return;
    size_t base = (size_t)t * KS;
    float mv[KS], lv[KS];
    float M = -INFINITY;
    #pragma unroll
    for (int c = 0; c < KS; c++) {
        mv[c] = pml[(base+c)*2];
        lv[c] = pml[(base+c)*2+1];
        M = fmaxf(M, mv[c]);
    }
    float w[KS]; float L = 0.0f;
    #pragma unroll
    for (int c = 0; c < KS; c++) { w[c] = ex2(mv[c] - M); L += w[c]*lv[c]; }
    float inv = 1.0f / L;
    int qrow = t >> 3, hh = t & 7;
    float* op = o + (size_t)qrow*DD + hh*DH;
    #pragma unroll
    for (int d = 0; d < 16; d++) {
        float s = 0.0f;
        #pragma unroll
        for (int c = 0; c < KS; c++) s += w[c] * pacc[(base+c)*16 + d];
        op[d] = s * inv;
    }
}

// ---------------- head: gather root, LN, dot ----------------
__global__ void head_kernel(const float* __restrict__ h, const float* __restrict__ g,
                            const float* __restrict__ bb, const float* __restrict__ w,
                            const float* __restrict__ hb, const int* __restrict__ root,
                            float* __restrict__ out) {
    __shared__ float sred[4];
    int t = threadIdx.x;
    for (int b = 0; b < BB; b++) {
        int row = root[b];
        float v = h[((size_t)b*NN + row)*DD + t];
        float mean = blockReduceSum128(v, sred) * (1.0f/DD);
        float d = v - mean;
        float var = blockReduceSum128(d*d, sred) * (1.0f/DD);
        float p = d * rsqrtf(var + EPS) * g[t] + bb[t];
        float s = blockReduceSum128(p * w[t], sred);
        if (t == 0) out[b] = s + hb[0];
    }
}

// ---------------- launch ----------------
extern "C" void kernel_launch(void* const* d_in, const int* in_sizes, int n_in,
                              void* d_out, int out_size) {
    const float* atom_embed = (const float*)d_in[0];
    const float* cons_embed = (const float*)d_in[1];
    const float* in_w   = (const float*)d_in[2];
    const float* in_b   = (const float*)d_in[3];
    const float* qkv_w  = (const float*)d_in[4];
    const float* qkv_b  = (const float*)d_in[5];
    const float* out_w  = (const float*)d_in[6];
    const float* out_b  = (const float*)d_in[7];
    const float* ln1_g  = (const float*)d_in[8];
    const float* ln1_b  = (const float*)d_in[9];
    const float* ln2_g  = (const float*)d_in[10];
    const float* ln2_b  = (const float*)d_in[11];
    const float* ff1_w  = (const float*)d_in[12];
    const float* ff1_b  = (const float*)d_in[13];
    const float* ff2_w  = (const float*)d_in[14];
    const float* ff2_b  = (const float*)d_in[15];
    const float* struct_bias = (const float*)d_in[16];
    const float* head_ln_g = (const float*)d_in[17];
    const float* head_ln_b = (const float*)d_in[18];
    const float* head_w = (const float*)d_in[19];
    const float* head_b = (const float*)d_in[20];
    const float* adjacency = (const float*)d_in[21];
    const unsigned char* is_atom_raw = (const unsigned char*)d_in[22];
    const int* atom_id  = (const int*)d_in[23];
    const unsigned char* mask_raw = (const unsigned char*)d_in[24];
    const int* root_idx = (const int*)d_in[25];
    float* outp = (float*)d_out;

    float *h, *x, *qkv, *o, *f, *pacc, *pml, *mean, *rstd;
    int *im, *mk;
    cudaGetSymbolAddress((void**)&h,  g_h);
    cudaGetSymbolAddress((void**)&x,  g_x);
    cudaGetSymbolAddress((void**)&qkv, g_qkv);
    cudaGetSymbolAddress((void**)&o,  g_o);
    cudaGetSymbolAddress((void**)&f,  g_f);
    cudaGetSymbolAddress((void**)&pacc, g_pacc);
    cudaGetSymbolAddress((void**)&pml,  g_pml);
    cudaGetSymbolAddress((void**)&mean, g_mean);
    cudaGetSymbolAddress((void**)&rstd, g_rstd);
    cudaGetSymbolAddress((void**)&im, g_isatom);
    cudaGetSymbolAddress((void**)&mk, g_mask);

    const int ATTN_SMEM = 25440*4;   // sK+sV (pitch132) + sS (8x64x33) + masks
    cudaFuncSetAttribute(attn_part_kernel, cudaFuncAttributeMaxDynamicSharedMemorySize, ATTN_SMEM);

    norm_bool_kernel<<<1, 256>>>(is_atom_raw, ROWS, im);
    norm_bool_kernel<<<1, 256>>>(mask_raw,    ROWS, mk);
    embed_kernel<<<ROWS, 128>>>(atom_embed, cons_embed, atom_id, im, x);

    gemm_kernel<0,32,false><<<dim3(2,128), 256>>>(x, in_w, in_b, nullptr, h,
                                                  ROWS, DD, DD, nullptr, nullptr, nullptr, nullptr);

    for (int l = 0; l < LL; l++) {
        stats_kernel<<<ROWS/8, 256>>>(h, mean, rstd);
        gemm_kernel<0,64,true><<<dim3(6,64), 256>>>(h, qkv_w + (size_t)l*3*DD*DD,
                                                    qkv_b + l*3*DD, nullptr, qkv,
                                                    ROWS, 3*DD, DD,
                                                    mean, rstd, ln1_g + l*DD, ln1_b + l*DD);
        attn_part_kernel<<<dim3(NN/64, KS*BB), 512, ATTN_SMEM>>>(qkv, adjacency, mk,
                                                                 struct_bias + l, pacc, pml);
        attn_reduce_kernel<<<ROWS*HH/256, 256>>>(pacc, pml, o);
        gemm_kernel<1,32,false><<<dim3(2,128), 256>>>(o, out_w + (size_t)l*DD*DD,
                                                      out_b + l*DD, h, h,
                                                      ROWS, DD, DD, nullptr, nullptr, nullptr, nullptr);
        stats_kernel<<<ROWS/8, 256>>>(h, mean, rstd);
        gemm_kernel<2,64,true><<<dim3(8,64), 256>>>(h, ff1_w + (size_t)l*4*DD*DD,
                                                    ff1_b + l*4*DD, nullptr, f,
                                                    ROWS, 4*DD, DD,
                                                    mean, rstd, ln2_g + l*DD, ln2_b + l*DD);
        gemm_kernel<1,32,false><<<dim3(2,128), 256>>>(f, ff2_w + (size_t)l*DD*4*DD,
                                                      ff2_b + l*DD, h, h,
                                                      ROWS, DD, 4*DD, nullptr, nullptr, nullptr, nullptr);
    }

    head_kernel<<<1, 128>>>(h, head_ln_g, head_ln_b, head_w, head_b, root_idx, outp);
}

// round 11
// speedup vs baseline: 1.4479x; 1.1697x over previous
#include <cuda_runtime.h>
#include <cuda_bf16.h>
#include <math.h>

// ---------------- problem constants ----------------
#define BB 2
#define NN 2048
#define DD 128
#define HH 8
#define DH 16
#define LL 3
#define ROWS (BB*NN)        // 4096
#define SCALE 0.25f         // 1/sqrt(16)
#define LOG2E 1.4426950408889634f
#define NEGL  (-1.5e9f)     // masked logit, log2 domain
#define EPS   1e-5f
#define KS    8             // key-split chunks
#define CHUNK (NN/KS)       // 256 keys per chunk

__device__ __forceinline__ float ex2(float x) {
    float r; asm("ex2.approx.ftz.f32 %0,%1;" : "=f"(r) : "f"(x)); return r;
}
__device__ __forceinline__ void cp4(unsigned dst, const float* src) {
    asm volatile("cp.async.ca.shared.global [%0], [%1], 4;" :: "r"(dst), "l"(src));
}
__device__ __forceinline__ void cp_commit() {
    asm volatile("cp.async.commit_group;" ::: "memory");
}
__device__ __forceinline__ void cp_wait1() {
    asm volatile("cp.async.wait_group 1;" ::: "memory");
}
__device__ __forceinline__ void cp_wait0() {
    asm volatile("cp.async.wait_group 0;" ::: "memory");
}

// ---------------- scratch (device globals; no allocation allowed) ----------
__device__ float g_h  [ROWS*DD];
__device__ float g_x  [ROWS*DD];
__device__ float g_qkv[ROWS*3*DD];
__device__ float g_o  [ROWS*DD];
__device__ float g_f  [ROWS*4*DD];
__device__ float g_pacc[ROWS*HH*KS*16];
__device__ float g_pml [ROWS*HH*KS*2];
__device__ float g_mean[ROWS];
__device__ float g_rstd[ROWS];
__device__ int   g_isatom[ROWS];
__device__ int   g_mask  [ROWS];

// ---------------- bool normalization (format-agnostic) ----------------
__global__ void norm_bool_kernel(const unsigned char* __restrict__ raw, int count,
                                 int* __restrict__ out) {
    __shared__ int s_other;
    if (threadIdx.x == 0) s_other = 0;
    __syncthreads();
    const unsigned int* w = (const unsigned int*)raw;
    int nw = count / 4;
    int other = 0;
    for (int i = threadIdx.x; i < nw; i += blockDim.x) {
        unsigned int v = w[i];
        if (v != 0u && v != 1u && v != 0x3f800000u) other = 1;
    }
    if (other) atomicOr(&s_other, 1);
    __syncthreads();
    bool byteFmt = (s_other != 0);
    for (int i = threadIdx.x; i < count; i += blockDim.x) {
        out[i] = byteFmt ? (raw[i] != 0) : (w[i] != 0u);
    }
}

// ---------------- embedding gather ----------------
__global__ void embed_kernel(const float* __restrict__ atom_embed,
                             const float* __restrict__ cons_embed,
                             const int* __restrict__ atom_id,
                             const int* __restrict__ isatom,
                             float* __restrict__ e) {
    int row = blockIdx.x, t = threadIdx.x;
    int id = atom_id[row];
    id = id < 0 ? 0 : (id > 31 ? 31 : id);
    float v = isatom[row] ? atom_embed[id*DD + t] : cons_embed[t];
    e[row*DD + t] = v;
}

// ---------------- block reduction helper (128 threads) ----------------
__device__ __forceinline__ float blockReduceSum128(float v, float* sred) {
    #pragma unroll
    for (int o = 16; o; o >>= 1) v += __shfl_xor_sync(0xffffffffu, v, o);
    int wid = threadIdx.x >> 5;
    if ((threadIdx.x & 31) == 0) sred[wid] = v;
    __syncthreads();
    float r = sred[0] + sred[1] + sred[2] + sred[3];
    __syncthreads();
    return r;
}

// ---------------- LN stats: warp per row (shuffles only) ----------------
__global__ void stats_kernel(const float* __restrict__ in,
                             float* __restrict__ mean, float* __restrict__ rstd) {
    int gw = (blockIdx.x*blockDim.x + threadIdx.x) >> 5;
    int lane = threadIdx.x & 31;
    float4 v = *(const float4*)(in + (size_t)gw*DD + lane*4);
    float s  = v.x + v.y + v.z + v.w;
    float s2 = v.x*v.x + v.y*v.y + v.z*v.z + v.w*v.w;
    #pragma unroll
    for (int o = 16; o; o >>= 1) {
        s  += __shfl_xor_sync(0xffffffffu, s,  o);
        s2 += __shfl_xor_sync(0xffffffffu, s2, o);
    }
    if (lane == 0) {
        float mu = s * (1.0f/DD);
        mean[gw] = mu;
        rstd[gw] = rsqrtf(s2 * (1.0f/DD) - mu*mu + EPS);
    }
}

// ---------------- SIMT GEMM (R4 lineage — proven fastest config) -----------
// C[M,Nc] = A'[M,K] @ W[Nc,K]^T + bias (+epilogue); A' = optional LayerNorm.
// MODE 0: +bias | MODE 1: +bias +res (res may alias C) | MODE 2: +bias, GELU
template<int MODE, int TM, bool LNA>
__global__ __launch_bounds__(256)
void gemm_kernel(const float* __restrict__ A, const float* __restrict__ W,
                 const float* __restrict__ bias, const float* __restrict__ res,
                 float* __restrict__ C, int M, int Nc, int K,
                 const float* __restrict__ meanp, const float* __restrict__ rstdp,
                 const float* __restrict__ lng, const float* __restrict__ lnb) {
    __shared__ float As[TM*33];
    __shared__ float Ws[64*33];
    const int t = threadIdx.x;
    const int tx = t & 15, ty = t >> 4;
    const int m0 = blockIdx.y * TM, n0 = blockIdx.x * 64;
    constexpr int RM = TM / 16;
    float acc[RM][4] = {};

    for (int k0 = 0; k0 < K; k0 += 32) {
        #pragma unroll
        for (int r = 0; r < TM/32; r++) {
            int idx = t + r*256;
            int row = idx >> 3, c4 = idx & 7;
            float4 va = *(const float4*)(A + (size_t)(m0+row)*K + k0 + c4*4);
            if (LNA) {
                float mu = meanp[m0+row], rs = rstdp[m0+row];
                float4 g4 = *(const float4*)(lng + k0 + c4*4);
                float4 b4 = *(const float4*)(lnb + k0 + c4*4);
                va.x = (va.x - mu)*rs*g4.x + b4.x;
                va.y = (va.y - mu)*rs*g4.y + b4.y;
                va.z = (va.z - mu)*rs*g4.z + b4.z;
                va.w = (va.w - mu)*rs*g4.w + b4.w;
            }
            float* da = As + row*33 + c4*4;
            da[0]=va.x; da[1]=va.y; da[2]=va.z; da[3]=va.w;
        }
        #pragma unroll
        for (int r = 0; r < 2; r++) {
            int idx = t + r*256;
            int row = idx >> 3, c4 = idx & 7;
            float4 vb = *(const float4*)(W + (size_t)(n0+row)*K + k0 + c4*4);
            float* db = Ws + row*33 + c4*4;
            db[0]=vb.x; db[1]=vb.y; db[2]=vb.z; db[3]=vb.w;
        }
        __syncthreads();
        #pragma unroll
        for (int kk = 0; kk < 32; kk++) {
            float a[RM], w[4];
            #pragma unroll
            for (int i = 0; i < RM; i++) a[i] = As[(ty*RM+i)*33 + kk];
            #pragma unroll
            for (int j = 0; j < 4; j++) w[j] = Ws[(tx*4+j)*33 + kk];
            #pragma unroll
            for (int i = 0; i < RM; i++)
                #pragma unroll
                for (int j = 0; j < 4; j++)
                    acc[i][j] += a[i] * w[j];
        }
        __syncthreads();
    }
    #pragma unroll
    for (int i = 0; i < RM; i++) {
        int r = m0 + ty*RM + i;
        #pragma unroll
        for (int j = 0; j < 4; j++) {
            int c = n0 + tx*4 + j;
            float v = acc[i][j] + bias[c];
            if (MODE == 1) v += res[(size_t)r*Nc + c];
            if (MODE == 2) v = 0.5f * v * (1.0f + erff(v * 0.70710678118654752f));
            C[(size_t)r*Nc + c] = v;
        }
    }
}

// ---------------- split-K flash attention: cp.async adjacency pipeline -----
// Grid (N/64, KS*B), 512 threads. Thread (hh=tid>>6, qi=tid&63) owns one
// (head, query-row). Adjacency streams into a 2-deep smem ring via LDGSTS
// (raw floats); mask logic is applied at read time (mq is a hoisted per-
// thread constant; key-mask addend is one broadcast LDS).
__global__ __launch_bounds__(512, 2)
void attn_part_kernel(const float* __restrict__ qkv, const float* __restrict__ adj,
                      const int* __restrict__ mask, const float* __restrict__ sbp,
                      float* __restrict__ pacc, float* __restrict__ pml) {
    extern __shared__ float sm[];
    float* sK    = sm;                    // 64*128
    float* sV    = sK + 64*128;           // 64*128
    float* sAdj0 = sV + 64*128;           // 64*65 (q-major, pitch 65)
    float* sAdj1 = sAdj0 + 64*65;
    float* sMk0  = sAdj1 + 64*65;         // 64 (mask addend 0/NEGL)
    float* sMk1  = sMk0 + 64;

    const int b = blockIdx.y >> 3, ck = blockIdx.y & 7;
    const int n0 = blockIdx.x * 64;
    const int tid = threadIdx.x;
    const int qi = tid & 63, hh = tid >> 6;
    const float sbl = (*sbp) * LOG2E;
    const float SC2 = SCALE * LOG2E;

    const float* adjb = adj + (size_t)b*NN*NN;
    const int* maskb = mask + b*NN;

    const int qrow = b*NN + n0 + qi;
    const int mq = maskb[n0 + qi];        // hoisted per-thread query mask
    float4 q4[4];
    {
        const float4* qp = (const float4*)(qkv + (size_t)qrow*384 + hh*DH);
        #pragma unroll
        for (int i = 0; i < 4; i++) q4[i] = qp[i];
    }

    float m = -INFINITY, l = 0.0f;
    float acc[16];
    #pragma unroll
    for (int d = 0; d < 16; d++) acc[d] = 0.0f;

    // adjacency copy thread mapping: thread t -> row t>>3, cols (t&7)*8 .. +7
    const int aq = tid >> 3, ak = (tid & 7) * 8;
    const int kBeg = ck*CHUNK, kEnd = (ck+1)*CHUNK;

    // prologue: issue adj copy for tile 0
    {
        const float* src = adjb + (size_t)(n0 + aq)*NN + kBeg + ak;
        unsigned dst = (unsigned)__cvta_generic_to_shared(sAdj0 + aq*65 + ak);
        #pragma unroll
        for (int j = 0; j < 8; j++) cp4(dst + j*4, src + j);
        cp_commit();
    }

    int db = 0;
    for (int k0 = kBeg; k0 < kEnd; k0 += 64) {
        float* sAdjCur = db ? sAdj1 : sAdj0;
        float* sMkCur  = db ? sMk1  : sMk0;

        // stage K/V tile (L2-hot qkv)
        #pragma unroll
        for (int r = 0; r < 4; r++) {
            int idx = tid + r*512;
            int row = idx >> 5, c4 = idx & 31;
            const float* base = qkv + (size_t)(b*NN + k0 + row)*384;
            *(float4*)(sK + row*128 + c4*4) = *(const float4*)(base + 128 + c4*4);
            *(float4*)(sV + row*128 + c4*4) = *(const float4*)(base + 256 + c4*4);
        }
        // key-mask addend for current tile
        if (tid < 64) sMkCur[tid] = maskb[k0 + tid] ? 0.0f : NEGL;

        // issue adj copy for next tile into the other buffer
        if (k0 + 64 < kEnd) {
            float* sAdjNxt = db ? sAdj0 : sAdj1;
            const float* src = adjb + (size_t)(n0 + aq)*NN + (k0 + 64) + ak;
            unsigned dst = (unsigned)__cvta_generic_to_shared(sAdjNxt + aq*65 + ak);
            #pragma unroll
            for (int j = 0; j < 8; j++) cp4(dst + j*4, src + j);
            cp_commit();
            cp_wait1();               // current tile's group done
        } else {
            cp_wait0();
        }
        __syncthreads();

        const bool tileDiag = (n0 == k0);
        for (int kj = 0; kj < 64; kj += 2) {
            const float4* kp0 = (const float4*)(sK + kj*128 + hh*DH);
            const float4* kp1 = (const float4*)(sK + (kj+1)*128 + hh*DH);
            float s0 = 0.0f, s1 = 0.0f;
            #pragma unroll
            for (int i = 0; i < 4; i++) {
                float4 k0v = kp0[i], k1v = kp1[i];
                s0 += q4[i].x*k0v.x + q4[i].y*k0v.y + q4[i].z*k0v.z + q4[i].w*k0v.w;
                s1 += q4[i].x*k1v.x + q4[i].y*k1v.y + q4[i].z*k1v.z + q4[i].w*k1v.w;
            }
            float ar0 = sAdjCur[qi*65 + kj];
            float ar1 = sAdjCur[qi*65 + kj + 1];
            float ma0 = mq ? sMkCur[kj]   : ((tileDiag && qi == kj)   ? 0.0f : NEGL);
            float ma1 = mq ? sMkCur[kj+1] : ((tileDiag && qi == kj+1) ? 0.0f : NEGL);
            s0 = fmaf(s0, SC2, fmaf(ar0, sbl, ma0));
            s1 = fmaf(s1, SC2, fmaf(ar1, sbl, ma1));

            float mn = fmaxf(m, fmaxf(s0, s1));
            if (mn > m) {
                float corr = ex2(m - mn);
                l *= corr;
                #pragma unroll
                for (int d = 0; d < 16; d++) acc[d] *= corr;
                m = mn;
            }
            float p0 = ex2(s0 - m);
            float p1 = ex2(s1 - m);
            l += p0 + p1;
            const float4* vp0 = (const float4*)(sV + kj*128 + hh*DH);
            const float4* vp1 = (const float4*)(sV + (kj+1)*128 + hh*DH);
            #pragma unroll
            for (int i = 0; i < 4; i++) {
                float4 v0 = vp0[i], v1 = vp1[i];
                acc[i*4+0] += p0*v0.x + p1*v1.x;
                acc[i*4+1] += p0*v0.y + p1*v1.y;
                acc[i*4+2] += p0*v0.z + p1*v1.z;
                acc[i*4+3] += p0*v0.w + p1*v1.w;
            }
        }
        __syncthreads();
        db ^= 1;
    }
    size_t p = ((size_t)qrow*HH + hh)*KS + ck;
    pml[p*2]   = m;
    pml[p*2+1] = l;
    #pragma unroll
    for (int d = 0; d < 16; d++) pacc[p*16 + d] = acc[d];
}

// ---------------- split-K reduce (base-2 weights) ----------------
__global__ void attn_reduce_kernel(const float* __restrict__ pacc,
                                   const float* __restrict__ pml,
                                   float* __restrict__ o) {
    int t = blockIdx.x * blockDim.x + threadIdx.x;     // 0..ROWS*HH-1
    if (t >= ROWS*HH) return;
    size_t base = (size_t)t * KS;
    float mv[KS], lv[KS];
    float M = -INFINITY;
    #pragma unroll
    for (int c = 0; c < KS; c++) {
        mv[c] = pml[(base+c)*2];
        lv[c] = pml[(base+c)*2+1];
        M = fmaxf(M, mv[c]);
    }
    float w[KS]; float L = 0.0f;
    #pragma unroll
    for (int c = 0; c < KS; c++) { w[c] = ex2(mv[c] - M); L += w[c]*lv[c]; }
    float inv = 1.0f / L;
    int qrow = t >> 3, hh = t & 7;
    float* op = o + (size_t)qrow*DD + hh*DH;
    #pragma unroll
    for (int d = 0; d < 16; d++) {
        float s = 0.0f;
        #pragma unroll
        for (int c = 0; c < KS; c++) s += w[c] * pacc[(base+c)*16 + d];
        op[d] = s * inv;
    }
}

// ---------------- head: gather root, LN, dot ----------------
__global__ void head_kernel(const float* __restrict__ h, const float* __restrict__ g,
                            const float* __restrict__ bb, const float* __restrict__ w,
                            const float* __restrict__ hb, const int* __restrict__ root,
                            float* __restrict__ out) {
    __shared__ float sred[4];
    int t = threadIdx.x;
    for (int b = 0; b < BB; b++) {
        int row = root[b];
        float v = h[((size_t)b*NN + row)*DD + t];
        float mean = blockReduceSum128(v, sred) * (1.0f/DD);
        float d = v - mean;
        float var = blockReduceSum128(d*d, sred) * (1.0f/DD);
        float p = d * rsqrtf(var + EPS) * g[t] + bb[t];
        float s = blockReduceSum128(p * w[t], sred);
        if (t == 0) out[b] = s + hb[0];
    }
}

// ---------------- launch ----------------
extern "C" void kernel_launch(void* const* d_in, const int* in_sizes, int n_in,
                              void* d_out, int out_size) {
    const float* atom_embed = (const float*)d_in[0];
    const float* cons_embed = (const float*)d_in[1];
    const float* in_w   = (const float*)d_in[2];
    const float* in_b   = (const float*)d_in[3];
    const float* qkv_w  = (const float*)d_in[4];
    const float* qkv_b  = (const float*)d_in[5];
    const float* out_w  = (const float*)d_in[6];
    const float* out_b  = (const float*)d_in[7];
    const float* ln1_g  = (const float*)d_in[8];
    const float* ln1_b  = (const float*)d_in[9];
    const float* ln2_g  = (const float*)d_in[10];
    const float* ln2_b  = (const float*)d_in[11];
    const float* ff1_w  = (const float*)d_in[12];
    const float* ff1_b  = (const float*)d_in[13];
    const float* ff2_w  = (const float*)d_in[14];
    const float* ff2_b  = (const float*)d_in[15];
    const float* struct_bias = (const float*)d_in[16];
    const float* head_ln_g = (const float*)d_in[17];
    const float* head_ln_b = (const float*)d_in[18];
    const float* head_w = (const float*)d_in[19];
    const float* head_b = (const float*)d_in[20];
    const float* adjacency = (const float*)d_in[21];
    const unsigned char* is_atom_raw = (const unsigned char*)d_in[22];
    const int* atom_id  = (const int*)d_in[23];
    const unsigned char* mask_raw = (const unsigned char*)d_in[24];
    const int* root_idx = (const int*)d_in[25];
    float* outp = (float*)d_out;

    float *h, *x, *qkv, *o, *f, *pacc, *pml, *mean, *rstd;
    int *im, *mk;
    cudaGetSymbolAddress((void**)&h,  g_h);
    cudaGetSymbolAddress((void**)&x,  g_x);
    cudaGetSymbolAddress((void**)&qkv, g_qkv);
    cudaGetSymbolAddress((void**)&o,  g_o);
    cudaGetSymbolAddress((void**)&f,  g_f);
    cudaGetSymbolAddress((void**)&pacc, g_pacc);
    cudaGetSymbolAddress((void**)&pml,  g_pml);
    cudaGetSymbolAddress((void**)&mean, g_mean);
    cudaGetSymbolAddress((void**)&rstd, g_rstd);
    cudaGetSymbolAddress((void**)&im, g_isatom);
    cudaGetSymbolAddress((void**)&mk, g_mask);

    // sK + sV + 2*sAdj(64*65) + 2*sMk(64)
    const int ATTN_SMEM = (64*128*2 + 2*64*65 + 2*64)*4;
    cudaFuncSetAttribute(attn_part_kernel, cudaFuncAttributeMaxDynamicSharedMemorySize, ATTN_SMEM);

    norm_bool_kernel<<<1, 256>>>(is_atom_raw, ROWS, im);
    norm_bool_kernel<<<1, 256>>>(mask_raw,    ROWS, mk);
    embed_kernel<<<ROWS, 128>>>(atom_embed, cons_embed, atom_id, im, x);

    gemm_kernel<0,32,false><<<dim3(2,128), 256>>>(x, in_w, in_b, nullptr, h,
                                                  ROWS, DD, DD, nullptr, nullptr, nullptr, nullptr);

    for (int l = 0; l < LL; l++) {
        stats_kernel<<<ROWS/8, 256>>>(h, mean, rstd);
        gemm_kernel<0,64,true><<<dim3(6,64), 256>>>(h, qkv_w + (size_t)l*3*DD*DD,
                                                    qkv_b + l*3*DD, nullptr, qkv,
                                                    ROWS, 3*DD, DD,
                                                    mean, rstd, ln1_g + l*DD, ln1_b + l*DD);
        attn_part_kernel<<<dim3(NN/64, KS*BB), 512, ATTN_SMEM>>>(qkv, adjacency, mk,
                                                                 struct_bias + l, pacc, pml);
        attn_reduce_kernel<<<ROWS*HH/256, 256>>>(pacc, pml, o);
        gemm_kernel<1,32,false><<<dim3(2,128), 256>>>(o, out_w + (size_t)l*DD*DD,
                                                      out_b + l*DD, h, h,
                                                      ROWS, DD, DD, nullptr, nullptr, nullptr, nullptr);
        stats_kernel<<<ROWS/8, 256>>>(h, mean, rstd);
        gemm_kernel<2,64,true><<<dim3(8,64), 256>>>(h, ff1_w + (size_t)l*4*DD*DD,
                                                    ff1_b + l*4*DD, nullptr, f,
                                                    ROWS, 4*DD, DD,
                                                    mean, rstd, ln2_g + l*DD, ln2_b + l*DD);
        gemm_kernel<1,32,false><<<dim3(2,128), 256>>>(f, ff2_w + (size_t)l*DD*4*DD,
                                                      ff2_b + l*DD, h, h,
                                                      ROWS, DD, 4*DD, nullptr, nullptr, nullptr, nullptr);
    }

    head_kernel<<<1, 128>>>(h, head_ln_g, head_ln_b, head_w, head_b, root_idx, outp);
}

// round 12
// speedup vs baseline: 1.8252x; 1.2606x over previous
#include <cuda_runtime.h>
#include <cuda_bf16.h>
#include <math.h>

// ---------------- problem constants ----------------
#define BB 2
#define NN 2048
#define DD 128
#define HH 8
#define DH 16
#define LL 3
#define ROWS (BB*NN)        // 4096
#define SCALE 0.25f         // 1/sqrt(16)
#define LOG2E 1.4426950408889634f
#define NEGL  (-1.5e9f)     // masked logit, log2 domain
#define EPS   1e-5f
#define KS    8             // key-split chunks
#define CHUNK (NN/KS)       // 256 keys per chunk

__device__ __forceinline__ float ex2(float x) {
    float r; asm("ex2.approx.ftz.f32 %0,%1;" : "=f"(r) : "f"(x)); return r;
}
__device__ __forceinline__ unsigned tf32c(float x) {
    unsigned r; asm("cvt.rna.tf32.f32 %0,%1;" : "=r"(r) : "f"(x)); return r;
}
__device__ __forceinline__ void mma8(float c[4], unsigned a0, unsigned a1,
                                     unsigned a2, unsigned a3,
                                     unsigned b0, unsigned b1) {
    asm volatile(
        "mma.sync.aligned.m16n8k8.row.col.f32.tf32.tf32.f32 "
        "{%0,%1,%2,%3},{%4,%5,%6,%7},{%8,%9},{%0,%1,%2,%3};"
        : "+f"(c[0]), "+f"(c[1]), "+f"(c[2]), "+f"(c[3])
        : "r"(a0), "r"(a1), "r"(a2), "r"(a3), "r"(b0), "r"(b1));
}
__device__ __forceinline__ void tsplit(float x, unsigned& hi, unsigned& lo) {
    hi = tf32c(x);
    lo = tf32c(x - __uint_as_float(hi));
}

// ---------------- scratch (device globals; no allocation allowed) ----------
__device__ float g_h  [ROWS*DD];
__device__ float g_x  [ROWS*DD];
__device__ float g_qkv[ROWS*3*DD];
__device__ float g_o  [ROWS*DD];
__device__ float g_f  [ROWS*4*DD];
__device__ float g_pacc[ROWS*HH*KS*16];
__device__ float g_pml [ROWS*HH*KS*2];
__device__ float g_mean[ROWS];
__device__ float g_rstd[ROWS];
__device__ int   g_isatom[ROWS];
__device__ int   g_mask  [ROWS];

// ---------------- bool normalization (format-agnostic) ----------------
__global__ void norm_bool_kernel(const unsigned char* __restrict__ raw, int count,
                                 int* __restrict__ out) {
    __shared__ int s_other;
    if (threadIdx.x == 0) s_other = 0;
    __syncthreads();
    const unsigned int* w = (const unsigned int*)raw;
    int nw = count / 4;
    int other = 0;
    for (int i = threadIdx.x; i < nw; i += blockDim.x) {
        unsigned int v = w[i];
        if (v != 0u && v != 1u && v != 0x3f800000u) other = 1;
    }
    if (other) atomicOr(&s_other, 1);
    __syncthreads();
    bool byteFmt = (s_other != 0);
    for (int i = threadIdx.x; i < count; i += blockDim.x) {
        out[i] = byteFmt ? (raw[i] != 0) : (w[i] != 0u);
    }
}

// ---------------- embedding gather ----------------
__global__ void embed_kernel(const float* __restrict__ atom_embed,
                             const float* __restrict__ cons_embed,
                             const int* __restrict__ atom_id,
                             const int* __restrict__ isatom,
                             float* __restrict__ e) {
    int row = blockIdx.x, t = threadIdx.x;
    int id = atom_id[row];
    id = id < 0 ? 0 : (id > 31 ? 31 : id);
    float v = isatom[row] ? atom_embed[id*DD + t] : cons_embed[t];
    e[row*DD + t] = v;
}

// ---------------- block reduction helper (128 threads) ----------------
__device__ __forceinline__ float blockReduceSum128(float v, float* sred) {
    #pragma unroll
    for (int o = 16; o; o >>= 1) v += __shfl_xor_sync(0xffffffffu, v, o);
    int wid = threadIdx.x >> 5;
    if ((threadIdx.x & 31) == 0) sred[wid] = v;
    __syncthreads();
    float r = sred[0] + sred[1] + sred[2] + sred[3];
    __syncthreads();
    return r;
}

// ---------------- LN stats: warp per row (shuffles only) ----------------
__global__ void stats_kernel(const float* __restrict__ in,
                             float* __restrict__ mean, float* __restrict__ rstd) {
    int gw = (blockIdx.x*blockDim.x + threadIdx.x) >> 5;
    int lane = threadIdx.x & 31;
    float4 v = *(const float4*)(in + (size_t)gw*DD + lane*4);
    float s  = v.x + v.y + v.z + v.w;
    float s2 = v.x*v.x + v.y*v.y + v.z*v.z + v.w*v.w;
    #pragma unroll
    for (int o = 16; o; o >>= 1) {
        s  += __shfl_xor_sync(0xffffffffu, s,  o);
        s2 += __shfl_xor_sync(0xffffffffu, s2, o);
    }
    if (lane == 0) {
        float mu = s * (1.0f/DD);
        mean[gw] = mu;
        rstd[gw] = rsqrtf(s2 * (1.0f/DD) - mu*mu + EPS);
    }
}

// ---------------- SIMT GEMM (R4 lineage — proven fastest config) -----------
// C[M,Nc] = A'[M,K] @ W[Nc,K]^T + bias (+epilogue); A' = optional LayerNorm.
// MODE 0: +bias | MODE 1: +bias +res (res may alias C) | MODE 2: +bias, GELU
template<int MODE, int TM, bool LNA>
__global__ __launch_bounds__(256)
void gemm_kernel(const float* __restrict__ A, const float* __restrict__ W,
                 const float* __restrict__ bias, const float* __restrict__ res,
                 float* __restrict__ C, int M, int Nc, int K,
                 const float* __restrict__ meanp, const float* __restrict__ rstdp,
                 const float* __restrict__ lng, const float* __restrict__ lnb) {
    __shared__ float As[TM*33];
    __shared__ float Ws[64*33];
    const int t = threadIdx.x;
    const int tx = t & 15, ty = t >> 4;
    const int m0 = blockIdx.y * TM, n0 = blockIdx.x * 64;
    constexpr int RM = TM / 16;
    float acc[RM][4] = {};

    for (int k0 = 0; k0 < K; k0 += 32) {
        #pragma unroll
        for (int r = 0; r < TM/32; r++) {
            int idx = t + r*256;
            int row = idx >> 3, c4 = idx & 7;
            float4 va = *(const float4*)(A + (size_t)(m0+row)*K + k0 + c4*4);
            if (LNA) {
                float mu = meanp[m0+row], rs = rstdp[m0+row];
                float4 g4 = *(const float4*)(lng + k0 + c4*4);
                float4 b4 = *(const float4*)(lnb + k0 + c4*4);
                va.x = (va.x - mu)*rs*g4.x + b4.x;
                va.y = (va.y - mu)*rs*g4.y + b4.y;
                va.z = (va.z - mu)*rs*g4.z + b4.z;
                va.w = (va.w - mu)*rs*g4.w + b4.w;
            }
            float* da = As + row*33 + c4*4;
            da[0]=va.x; da[1]=va.y; da[2]=va.z; da[3]=va.w;
        }
        #pragma unroll
        for (int r = 0; r < 2; r++) {
            int idx = t + r*256;
            int row = idx >> 3, c4 = idx & 7;
            float4 vb = *(const float4*)(W + (size_t)(n0+row)*K + k0 + c4*4);
            float* db = Ws + row*33 + c4*4;
            db[0]=vb.x; db[1]=vb.y; db[2]=vb.z; db[3]=vb.w;
        }
        __syncthreads();
        #pragma unroll
        for (int kk = 0; kk < 32; kk++) {
            float a[RM], w[4];
            #pragma unroll
            for (int i = 0; i < RM; i++) a[i] = As[(ty*RM+i)*33 + kk];
            #pragma unroll
            for (int j = 0; j < 4; j++) w[j] = Ws[(tx*4+j)*33 + kk];
            #pragma unroll
            for (int i = 0; i < RM; i++)
                #pragma unroll
                for (int j = 0; j < 4; j++)
                    acc[i][j] += a[i] * w[j];
        }
        __syncthreads();
    }
    #pragma unroll
    for (int i = 0; i < RM; i++) {
        int r = m0 + ty*RM + i;
        #pragma unroll
        for (int j = 0; j < 4; j++) {
            int c = n0 + tx*4 + j;
            float v = acc[i][j] + bias[c];
            if (MODE == 1) v += res[(size_t)r*Nc + c];
            if (MODE == 2) v = 0.5f * v * (1.0f + erff(v * 0.70710678118654752f));
            C[(size_t)r*Nc + c] = v;
        }
    }
}

// ---------------- full tensor-core flash attention (split-K partials) ------
// Grid (NN/32, KS*BB), 256 threads = 8 warps = 8 heads. Warp handles 32 q-rows
// x CHUNK keys for its head. QK and PV both via 3xTF32 m16n8k8. Softmax on
// C-fragments (quad shfl reductions). PV consumes P directly from S fragments
// via the sigma key-permutation (C cols {2t4,2t4+1} == A k-cols {t4,t4+4}
// when V fragment keys are read at {2t4, 2t4+1}). No smem, no block syncs.
__global__ __launch_bounds__(256)
void attn_tc_kernel(const float* __restrict__ qkv, const float* __restrict__ adj,
                    const int* __restrict__ mask, const float* __restrict__ sbp,
                    float* __restrict__ pacc, float* __restrict__ pml) {
    const int b = blockIdx.y >> 3, ck = blockIdx.y & 7;
    const int n0 = blockIdx.x * 32;
    const int tid = threadIdx.x;
    const int hh = tid >> 5, lane = tid & 31;
    const int g = lane >> 2, t4 = lane & 3;
    const float sbl = (*sbp) * LOG2E;
    const float SC2 = SCALE * LOG2E;
    const float* adjb = adj + (size_t)b*NN*NN;
    const int* maskb = mask + b*NN;
    const float* qkvb = qkv + (size_t)b*NN*384;

    // hoisted Q A-fragments (hi/lo): rows mt*16+{g,g+8}, dims hh*16+ks*8+{t4,t4+4}
    unsigned qh[2][2][4], ql[2][2][4];
    #pragma unroll
    for (int mt = 0; mt < 2; mt++)
        #pragma unroll
        for (int ks = 0; ks < 2; ks++) {
            const float* r0 = qkvb + (size_t)(n0 + mt*16 + g)*384 + hh*16 + ks*8;
            const float* r8 = r0 + 8*384;
            tsplit(r0[t4],   qh[mt][ks][0], ql[mt][ks][0]);
            tsplit(r8[t4],   qh[mt][ks][1], ql[mt][ks][1]);
            tsplit(r0[t4+4], qh[mt][ks][2], ql[mt][ks][2]);
            tsplit(r8[t4+4], qh[mt][ks][3], ql[mt][ks][3]);
        }
    // hoisted query-row masks for this thread's 4 rows
    int mqr[2][2];
    #pragma unroll
    for (int mt = 0; mt < 2; mt++)
        #pragma unroll
        for (int hf = 0; hf < 2; hf++)
            mqr[mt][hf] = maskb[n0 + mt*16 + g + hf*8];

    float mrun[2][2], lrun[2][2];
    #pragma unroll
    for (int mt = 0; mt < 2; mt++)
        #pragma unroll
        for (int hf = 0; hf < 2; hf++) { mrun[mt][hf] = -INFINITY; lrun[mt][hf] = 0.0f; }
    float co[2][2][4] = {};            // O accum: [mt][dim-ntile][frag]

    const int kBeg = ck*CHUNK, kEnd = ck*CHUNK + CHUNK;
    for (int k0 = kBeg; k0 < kEnd; k0 += 32) {
        // ---- S = Q K^T (3xTF32), K fragments direct from gmem ----
        float s[2][4][4] = {};
        #pragma unroll
        for (int nt = 0; nt < 4; nt++)
            #pragma unroll
            for (int ks = 0; ks < 2; ks++) {
                const float* kr = qkvb + (size_t)(k0 + nt*8 + g)*384 + 128 + hh*16 + ks*8;
                unsigned bh0, bl0, bh1, bl1;
                tsplit(kr[t4],   bh0, bl0);
                tsplit(kr[t4+4], bh1, bl1);
                #pragma unroll
                for (int mt = 0; mt < 2; mt++) {
                    mma8(s[mt][nt], qh[mt][ks][0], qh[mt][ks][1], qh[mt][ks][2], qh[mt][ks][3], bh0, bh1);
                    mma8(s[mt][nt], ql[mt][ks][0], ql[mt][ks][1], ql[mt][ks][2], ql[mt][ks][3], bh0, bh1);
                    mma8(s[mt][nt], qh[mt][ks][0], qh[mt][ks][1], qh[mt][ks][2], qh[mt][ks][3], bl0, bl1);
                }
            }
        // ---- epilogue: scale + struct_bias*adj + mask (log2 domain) ----
        #pragma unroll
        for (int nt = 0; nt < 4; nt++) {
            int gk = k0 + nt*8 + t4*2;
            int mk0 = maskb[gk], mk1 = maskb[gk+1];
            #pragma unroll
            for (int mt = 0; mt < 2; mt++)
                #pragma unroll
                for (int hf = 0; hf < 2; hf++) {
                    int gq = n0 + mt*16 + g + hf*8;
                    float2 a2 = *(const float2*)(adjb + (size_t)gq*NN + gk);
                    bool ok0 = mqr[mt][hf] ? (mk0 != 0) : (gq == gk);
                    bool ok1 = mqr[mt][hf] ? (mk1 != 0) : (gq == gk+1);
                    s[mt][nt][hf*2]   = fmaf(s[mt][nt][hf*2],   SC2, fmaf(a2.x, sbl, ok0 ? 0.0f : NEGL));
                    s[mt][nt][hf*2+1] = fmaf(s[mt][nt][hf*2+1], SC2, fmaf(a2.y, sbl, ok1 ? 0.0f : NEGL));
                }
        }
        // ---- online softmax on fragments (quad shfl row reductions) ----
        #pragma unroll
        for (int mt = 0; mt < 2; mt++)
            #pragma unroll
            for (int hf = 0; hf < 2; hf++) {
                float mloc = s[mt][0][hf*2];
                mloc = fmaxf(mloc, s[mt][0][hf*2+1]);
                #pragma unroll
                for (int nt = 1; nt < 4; nt++) {
                    mloc = fmaxf(mloc, s[mt][nt][hf*2]);
                    mloc = fmaxf(mloc, s[mt][nt][hf*2+1]);
                }
                mloc = fmaxf(mloc, __shfl_xor_sync(0xffffffffu, mloc, 1));
                mloc = fmaxf(mloc, __shfl_xor_sync(0xffffffffu, mloc, 2));
                float mn = fmaxf(mrun[mt][hf], mloc);
                float corr = ex2(mrun[mt][hf] - mn);
                mrun[mt][hf] = mn;
                #pragma unroll
                for (int nt2 = 0; nt2 < 2; nt2++) {
                    co[mt][nt2][hf*2]   *= corr;
                    co[mt][nt2][hf*2+1] *= corr;
                }
                float ls = 0.0f;
                #pragma unroll
                for (int nt = 0; nt < 4; nt++) {
                    float p0 = ex2(s[mt][nt][hf*2]   - mn);
                    float p1 = ex2(s[mt][nt][hf*2+1] - mn);
                    s[mt][nt][hf*2] = p0; s[mt][nt][hf*2+1] = p1;
                    ls += p0 + p1;
                }
                ls += __shfl_xor_sync(0xffffffffu, ls, 1);
                ls += __shfl_xor_sync(0xffffffffu, ls, 2);
                lrun[mt][hf] = lrun[mt][hf]*corr + ls;
            }
        // ---- O += P V (3xTF32); P from S fragments via sigma permutation ----
        #pragma unroll
        for (int ntk = 0; ntk < 4; ntk++) {
            unsigned ah[2][4], al[2][4];
            #pragma unroll
            for (int mt = 0; mt < 2; mt++) {
                tsplit(s[mt][ntk][0], ah[mt][0], al[mt][0]);   // row g,   key 2t4   -> A kcol t4
                tsplit(s[mt][ntk][2], ah[mt][1], al[mt][1]);   // row g+8, key 2t4
                tsplit(s[mt][ntk][1], ah[mt][2], al[mt][2]);   // row g,   key 2t4+1 -> A kcol t4+4
                tsplit(s[mt][ntk][3], ah[mt][3], al[mt][3]);   // row g+8, key 2t4+1
            }
            #pragma unroll
            for (int nt2 = 0; nt2 < 2; nt2++) {
                const float* vr = qkvb + (size_t)(k0 + ntk*8 + 2*t4)*384 + 256 + hh*16 + nt2*8 + g;
                unsigned vh0, vl0, vh1, vl1;
                tsplit(vr[0],   vh0, vl0);     // V[key 2t4  ][dim]
                tsplit(vr[384], vh1, vl1);     // V[key 2t4+1][dim]
                #pragma unroll
                for (int mt = 0; mt < 2; mt++) {
                    mma8(co[mt][nt2], ah[mt][0], ah[mt][1], ah[mt][2], ah[mt][3], vh0, vh1);
                    mma8(co[mt][nt2], al[mt][0], al[mt][1], al[mt][2], al[mt][3], vh0, vh1);
                    mma8(co[mt][nt2], ah[mt][0], ah[mt][1], ah[mt][2], ah[mt][3], vl0, vl1);
                }
            }
        }
    }
    // ---- write split-K partials ----
    #pragma unroll
    for (int mt = 0; mt < 2; mt++)
        #pragma unroll
        for (int hf = 0; hf < 2; hf++) {
            int q = n0 + mt*16 + g + hf*8;
            size_t p = (((size_t)(b*NN + q))*HH + hh)*KS + ck;
            if (t4 == 0) {
                pml[p*2]   = mrun[mt][hf];
                pml[p*2+1] = lrun[mt][hf];
            }
            #pragma unroll
            for (int nt2 = 0; nt2 < 2; nt2++)
                *(float2*)(pacc + p*16 + nt2*8 + t4*2) =
                    make_float2(co[mt][nt2][hf*2], co[mt][nt2][hf*2+1]);
        }
}

// ---------------- split-K reduce (base-2 weights) ----------------
__global__ void attn_reduce_kernel(const float* __restrict__ pacc,
                                   const float* __restrict__ pml,
                                   float* __restrict__ o) {
    int t = blockIdx.x * blockDim.x + threadIdx.x;     // 0..ROWS*HH-1
    if (t >= ROWS*HH) return;
    size_t base = (size_t)t * KS;
    float mv[KS], lv[KS];
    float M = -INFINITY;
    #pragma unroll
    for (int c = 0; c < KS; c++) {
        mv[c] = pml[(base+c)*2];
        lv[c] = pml[(base+c)*2+1];
        M = fmaxf(M, mv[c]);
    }
    float w[KS]; float L = 0.0f;
    #pragma unroll
    for (int c = 0; c < KS; c++) { w[c] = ex2(mv[c] - M); L += w[c]*lv[c]; }
    float inv = 1.0f / L;
    int qrow = t >> 3, hh = t & 7;
    float* op = o + (size_t)qrow*DD + hh*DH;
    #pragma unroll
    for (int d = 0; d < 16; d++) {
        float s = 0.0f;
        #pragma unroll
        for (int c = 0; c < KS; c++) s += w[c] * pacc[(base+c)*16 + d];
        op[d] = s * inv;
    }
}

// ---------------- head: gather root, LN, dot ----------------
__global__ void head_kernel(const float* __restrict__ h, const float* __restrict__ g,
                            const float* __restrict__ bb, const float* __restrict__ w,
                            const float* __restrict__ hb, const int* __restrict__ root,
                            float* __restrict__ out) {
    __shared__ float sred[4];
    int t = threadIdx.x;
    for (int b = 0; b < BB; b++) {
        int row = root[b];
        float v = h[((size_t)b*NN + row)*DD + t];
        float mean = blockReduceSum128(v, sred) * (1.0f/DD);
        float d = v - mean;
        float var = blockReduceSum128(d*d, sred) * (1.0f/DD);
        float p = d * rsqrtf(var + EPS) * g[t] + bb[t];
        float s = blockReduceSum128(p * w[t], sred);
        if (t == 0) out[b] = s + hb[0];
    }
}

// ---------------- launch ----------------
extern "C" void kernel_launch(void* const* d_in, const int* in_sizes, int n_in,
                              void* d_out, int out_size) {
    const float* atom_embed = (const float*)d_in[0];
    const float* cons_embed = (const float*)d_in[1];
    const float* in_w   = (const float*)d_in[2];
    const float* in_b   = (const float*)d_in[3];
    const float* qkv_w  = (const float*)d_in[4];
    const float* qkv_b  = (const float*)d_in[5];
    const float* out_w  = (const float*)d_in[6];
    const float* out_b  = (const float*)d_in[7];
    const float* ln1_g  = (const float*)d_in[8];
    const float* ln1_b  = (const float*)d_in[9];
    const float* ln2_g  = (const float*)d_in[10];
    const float* ln2_b  = (const float*)d_in[11];
    const float* ff1_w  = (const float*)d_in[12];
    const float* ff1_b  = (const float*)d_in[13];
    const float* ff2_w  = (const float*)d_in[14];
    const float* ff2_b  = (const float*)d_in[15];
    const float* struct_bias = (const float*)d_in[16];
    const float* head_ln_g = (const float*)d_in[17];
    const float* head_ln_b = (const float*)d_in[18];
    const float* head_w = (const float*)d_in[19];
    const float* head_b = (const float*)d_in[20];
    const float* adjacency = (const float*)d_in[21];
    const unsigned char* is_atom_raw = (const unsigned char*)d_in[22];
    const int* atom_id  = (const int*)d_in[23];
    const unsigned char* mask_raw = (const unsigned char*)d_in[24];
    const int* root_idx = (const int*)d_in[25];
    float* outp = (float*)d_out;

    float *h, *x, *qkv, *o, *f, *pacc, *pml, *mean, *rstd;
    int *im, *mk;
    cudaGetSymbolAddress((void**)&h,  g_h);
    cudaGetSymbolAddress((void**)&x,  g_x);
    cudaGetSymbolAddress((void**)&qkv, g_qkv);
    cudaGetSymbolAddress((void**)&o,  g_o);
    cudaGetSymbolAddress((void**)&f,  g_f);
    cudaGetSymbolAddress((void**)&pacc, g_pacc);
    cudaGetSymbolAddress((void**)&pml,  g_pml);
    cudaGetSymbolAddress((void**)&mean, g_mean);
    cudaGetSymbolAddress((void**)&rstd, g_rstd);
    cudaGetSymbolAddress((void**)&im, g_isatom);
    cudaGetSymbolAddress((void**)&mk, g_mask);

    norm_bool_kernel<<<1, 256>>>(is_atom_raw, ROWS, im);
    norm_bool_kernel<<<1, 256>>>(mask_raw,    ROWS, mk);
    embed_kernel<<<ROWS, 128>>>(atom_embed, cons_embed, atom_id, im, x);

    gemm_kernel<0,32,false><<<dim3(2,128), 256>>>(x, in_w, in_b, nullptr, h,
                                                  ROWS, DD, DD, nullptr, nullptr, nullptr, nullptr);

    for (int l = 0; l < LL; l++) {
        stats_kernel<<<ROWS/8, 256>>>(h, mean, rstd);
        gemm_kernel<0,64,true><<<dim3(6,64), 256>>>(h, qkv_w + (size_t)l*3*DD*DD,
                                                    qkv_b + l*3*DD, nullptr, qkv,
                                                    ROWS, 3*DD, DD,
                                                    mean, rstd, ln1_g + l*DD, ln1_b + l*DD);
        attn_tc_kernel<<<dim3(NN/32, KS*BB), 256>>>(qkv, adjacency, mk,
                                                    struct_bias + l, pacc, pml);
        attn_reduce_kernel<<<ROWS*HH/256, 256>>>(pacc, pml, o);
        gemm_kernel<1,32,false><<<dim3(2,128), 256>>>(o, out_w + (size_t)l*DD*DD,
                                                      out_b + l*DD, h, h,
                                                      ROWS, DD, DD, nullptr, nullptr, nullptr, nullptr);
        stats_kernel<<<ROWS/8, 256>>>(h, mean, rstd);
        gemm_kernel<2,64,true><<<dim3(8,64), 256>>>(h, ff1_w + (size_t)l*4*DD*DD,
                                                    ff1_b + l*4*DD, nullptr, f,
                                                    ROWS, 4*DD, DD,
                                                    mean, rstd, ln2_g + l*DD, ln2_b + l*DD);
        gemm_kernel<1,32,false><<<dim3(2,128), 256>>>(f, ff2_w + (size_t)l*DD*4*DD,
                                                      ff2_b + l*DD, h, h,
                                                      ROWS, DD, 4*DD, nullptr, nullptr, nullptr, nullptr);
    }

    head_kernel<<<1, 128>>>(h, head_ln_g, head_ln_b, head_w, head_b, root_idx, outp);
}